// round 2
// baseline (speedup 1.0000x reference)
#include <cuda_runtime.h>
#include <math_constants.h>
#include <cstdint>

// Problem constants
#define NROWS 8192      // B*H*W = 8*32*32
#define NE    16384     // number of embeddings
#define KDIM  256       // embedding dim
#define BM    128
#define BN    128
#define KT    16
#define NBLK  (NE / BN)     // 128
#define MBLK  (NROWS / BM)  // 64
#define NZQ   2097152       // 8*256*32*32
#define NOUTBLOCKS (NZQ / 256)  // 8192

// Scratch (device globals; no allocation allowed)
__device__ float  g_t1[NROWS];            // row squared norms of z (transposed view)
__device__ float  g_pd[NROWS * NBLK];     // partial min distance per (row, colblock)
__device__ int    g_pi[NROWS * NBLK];     // partial argmin index per (row, colblock)
__device__ int    g_idx[NROWS];           // final argmin per row
__device__ double g_lpart[NOUTBLOCKS];    // per-block loss partial sums

// ---------------------------------------------------------------------------
// K1: per-row ||z||^2. Row r = b*1024 + hw, channel c strided by 1024 in z.
// Any fp32 accumulation order is fine (lattice argument: only the binade of t1
// matters for the rounding grid of t1 - x).
// ---------------------------------------------------------------------------
__global__ void k_prep(const float* __restrict__ z) {
    int row = blockIdx.x * blockDim.x + threadIdx.x;
    if (row >= NROWS) return;
    int b  = row >> 10;
    int hw = row & 1023;
    const float* p = z + (size_t)b * 262144 + hw;
    float s = 0.0f;
#pragma unroll 8
    for (int c = 0; c < KDIM; c++) {
        float v = p[(size_t)c * 1024];
        s = fmaf(v, v, s);
    }
    g_t1[row] = s;
}

// ---------------------------------------------------------------------------
// K2: tiled GEMM (dot of z-rows with emb-rows) fused with per-row argmin of
// d = fl(t1 - fl(2*dot)). 128x128 tile, KT=16 k-steps, double buffered,
// register-staged global loads. 256 threads, 8x8 microtile each.
// Thread (tx,ty), tx=tid&15 selects 8 candidate cols, ty=tid>>4 selects 8 rows.
// ---------------------------------------------------------------------------
__global__ void __launch_bounds__(256, 2) k_gemm(const float* __restrict__ z,
                                                 const float* __restrict__ emb) {
    __shared__ float As[2][KT][BM + 1];   // [k][m], stride 129: conflict-free STS
    __shared__ float Bs[2][KT][BN + 1];   // [k][n]

    const int tid  = threadIdx.x;
    const int tx   = tid & 15;
    const int ty   = tid >> 4;
    const int nblk = blockIdx.x;
    const int mblk = blockIdx.y;
    const int m0   = mblk * BM;
    const int n0   = nblk * BN;
    const int b    = m0 >> 10;      // all 128 rows of this block share the same batch b
    const int hw0  = m0 & 1023;

    const float* zb = z   + (size_t)b * 262144 + hw0;   // + k*1024 + m
    const float* eb = emb + (size_t)n0 * 256;           // + n*256  + k

    float acc[8][8];
#pragma unroll
    for (int i = 0; i < 8; i++)
#pragma unroll
        for (int j = 0; j < 8; j++) acc[i][j] = 0.0f;

    // loader index decomposition (8 elements per thread per tile per matrix)
    // A: m = idx&127 (lane-consecutive -> coalesced 512B), k = idx>>7
    // B: k = idx&15  (lane-consecutive -> coalesced 64B),  n = idx>>4
    float ra[8], rb[8];

    // --- load tile 0 ---
#pragma unroll
    for (int p = 0; p < 8; p++) {
        int idx = tid + p * 256;
        int am = idx & 127, ak = idx >> 7;
        ra[p] = zb[(size_t)ak * 1024 + am];
        int bk = idx & 15, bn = idx >> 4;
        rb[p] = eb[(size_t)bn * 256 + bk];
    }
#pragma unroll
    for (int p = 0; p < 8; p++) {
        int idx = tid + p * 256;
        As[0][idx >> 7][idx & 127] = ra[p];
        Bs[0][idx & 15][idx >> 4]  = rb[p];
    }
    __syncthreads();

    const int NKT = KDIM / KT;  // 16
#pragma unroll 1
    for (int t = 0; t < NKT; t++) {
        const int cur = t & 1;
        const int nxt = cur ^ 1;

        // issue global loads for next tile (latency hidden under compute)
        if (t + 1 < NKT) {
            const int k0 = (t + 1) * KT;
#pragma unroll
            for (int p = 0; p < 8; p++) {
                int idx = tid + p * 256;
                int am = idx & 127, ak = idx >> 7;
                ra[p] = zb[(size_t)(k0 + ak) * 1024 + am];
                int bk = idx & 15, bn = idx >> 4;
                rb[p] = eb[(size_t)bn * 256 + k0 + bk];
            }
        }

        // compute current tile
        const float* Ab = &As[cur][0][ty * 8];
        const float* Bb = &Bs[cur][0][tx * 8];
#pragma unroll 4
        for (int k = 0; k < KT; k++) {
            float a[8], bb[8];
#pragma unroll
            for (int i = 0; i < 8; i++) a[i] = Ab[k * (BM + 1) + i];
#pragma unroll
            for (int j = 0; j < 8; j++) bb[j] = Bb[k * (BN + 1) + j];
#pragma unroll
            for (int i = 0; i < 8; i++)
#pragma unroll
                for (int j = 0; j < 8; j++)
                    acc[i][j] = fmaf(a[i], bb[j], acc[i][j]);
        }

        // stage next tile into smem
        if (t + 1 < NKT) {
#pragma unroll
            for (int p = 0; p < 8; p++) {
                int idx = tid + p * 256;
                As[nxt][idx >> 7][idx & 127] = ra[p];
                Bs[nxt][idx & 15][idx >> 4]  = rb[p];
            }
        }
        __syncthreads();
    }

    // ---- fused argmin epilogue ----
    // d = fl(t1 - fl(2*dot)); strict < with ascending-index scan everywhere
    // reproduces jnp.argmin first-occurrence semantics.
    float t1v[8];
#pragma unroll
    for (int i = 0; i < 8; i++) t1v[i] = g_t1[m0 + ty * 8 + i];

    // reuse smem (synced above after last compute iteration)
    float* sd = &As[0][0][0];          // [128][16] floats
    int*   si = (int*)&Bs[0][0][0];    // [128][16] ints

#pragma unroll
    for (int i = 0; i < 8; i++) {
        float bd = CUDART_INF_F;
        int   bj = 0;
#pragma unroll
        for (int j = 0; j < 8; j++) {               // ascending local n
            float x = __fmul_rn(2.0f, acc[i][j]);
            float d = __fsub_rn(t1v[i], x);
            if (d < bd) { bd = d; bj = tx * 8 + j; }
        }
        sd[(ty * 8 + i) * 16 + tx] = bd;
        si[(ty * 8 + i) * 16 + tx] = bj;
    }
    __syncthreads();

    if (tid < 128) {
        float bd = CUDART_INF_F;
        int   bj = 0;
#pragma unroll
        for (int x = 0; x < 16; x++) {              // ascending tx = ascending n
            float d = sd[tid * 16 + x];
            if (d < bd) { bd = d; bj = si[tid * 16 + x]; }
        }
        g_pd[(size_t)(m0 + tid) * NBLK + nblk] = bd;
        g_pi[(size_t)(m0 + tid) * NBLK + nblk] = n0 + bj;
    }
}

// ---------------------------------------------------------------------------
// K3: combine 128 column-block partials per row. Lexicographic (d, idx) min:
// for equal floats d, smallest global index == first occurrence.
// One warp per row.
// ---------------------------------------------------------------------------
__global__ void k_combine(float* __restrict__ out, int out_size) {
    int row  = blockIdx.x * 8 + (threadIdx.x >> 5);
    int lane = threadIdx.x & 31;
    if (row >= NROWS) return;

    float bd = CUDART_INF_F;
    int   bi = 0x7fffffff;
    const float* pd = g_pd + (size_t)row * NBLK;
    const int*   pi = g_pi + (size_t)row * NBLK;
#pragma unroll
    for (int x = lane; x < NBLK; x += 32) {
        float d = pd[x];
        int   i = pi[x];
        if (d < bd || (d == bd && i < bi)) { bd = d; bi = i; }
    }
#pragma unroll
    for (int o = 16; o > 0; o >>= 1) {
        float od = __shfl_down_sync(0xffffffffu, bd, o);
        int   oi = __shfl_down_sync(0xffffffffu, bi, o);
        if (od < bd || (od == bd && oi < bi)) { bd = od; bi = oi; }
    }
    if (lane == 0) {
        g_idx[row] = bi;
        int pos = NZQ + 1 + row;
        if (pos < out_size) out[pos] = (float)bi;   // indices after z_q and loss
    }
}

// ---------------------------------------------------------------------------
// K4: z_q gather + straight-through output + per-block loss partials.
// Output element at pos = b*262144 + c*1024 + hw (b,c,h,w layout, matching z).
// STE emulated exactly in fp32: out = fl(z + fl(zq - z)).
// Loss partial: sum of fl32((zq - z)^2) accumulated in double (deterministic).
// ---------------------------------------------------------------------------
__global__ void k_out(const float* __restrict__ z, const float* __restrict__ emb,
                      float* __restrict__ out, int out_size) {
    int pos = blockIdx.x * 256 + threadIdx.x;
    double contrib = 0.0;
    if (pos < NZQ) {
        int b   = pos >> 18;          // / 262144
        int r   = pos & 262143;
        int c   = r >> 10;
        int hw  = r & 1023;
        int row = (b << 10) + hw;
        int idx = g_idx[row];
        float ztv   = z[pos];
        float zq    = emb[(size_t)idx * 256 + c];
        float delta = __fsub_rn(zq, ztv);
        if (pos < out_size) out[pos] = __fadd_rn(ztv, delta);
        float sq = __fmul_rn(delta, delta);
        contrib = (double)sq;
    }
    __shared__ double s[256];
    s[threadIdx.x] = contrib;
    __syncthreads();
#pragma unroll
    for (int o = 128; o > 0; o >>= 1) {
        if (threadIdx.x < o) s[threadIdx.x] += s[threadIdx.x + o];
        __syncthreads();
    }
    if (threadIdx.x == 0) g_lpart[blockIdx.x] = s[0];
}

// ---------------------------------------------------------------------------
// K5: deterministic final loss reduction. loss = fl(m + fl(0.25*m)),
// m = fl32(sum/NZQ). Single block, fixed order.
// ---------------------------------------------------------------------------
__global__ void k_loss(float* __restrict__ out, int out_size) {
    __shared__ double s[256];
    double acc = 0.0;
    for (int x = threadIdx.x; x < NOUTBLOCKS; x += 256) acc += g_lpart[x];
    s[threadIdx.x] = acc;
    __syncthreads();
#pragma unroll
    for (int o = 128; o > 0; o >>= 1) {
        if (threadIdx.x < o) s[threadIdx.x] += s[threadIdx.x + o];
        __syncthreads();
    }
    if (threadIdx.x == 0 && NZQ < out_size) {
        float m = (float)(s[0] / (double)NZQ);
        out[NZQ] = __fadd_rn(m, __fmul_rn(0.25f, m));
    }
}

// ---------------------------------------------------------------------------
extern "C" void kernel_launch(void* const* d_in, const int* in_sizes, int n_in,
                              void* d_out, int out_size) {
    const float* z   = (const float*)d_in[0];   // [8,256,32,32]
    const float* emb = (const float*)d_in[1];   // [16384,256]
    float* out = (float*)d_out;

    k_prep<<<NROWS / 256, 256>>>(z);

    dim3 grid(NBLK, MBLK);
    k_gemm<<<grid, 256>>>(z, emb);

    k_combine<<<NROWS / 8, 256>>>(out, out_size);
    k_out<<<NOUTBLOCKS, 256>>>(z, emb, out, out_size);
    k_loss<<<1, 256>>>(out, out_size);
}

// round 5
// speedup vs baseline: 1.6474x; 1.6474x over previous
#include <cuda_runtime.h>
#include <math_constants.h>
#include <cstdint>

typedef unsigned long long ull;

// Problem constants
#define NROWS 8192      // B*H*W = 8*32*32
#define NE    16384     // number of embeddings
#define KDIM  256       // embedding dim
#define BM    128
#define BN    128
#define KT    16
#define LDP   132       // smem row stride (floats): 16B-aligned, conflict-free chunks
#define NBLK  (NE / BN)     // 128
#define MBLK  (NROWS / BM)  // 64
#define NZQ   2097152       // 8*256*32*32
#define NOUTBLOCKS (NZQ / 256)  // 8192

// Scratch (device globals; no allocation allowed)
__device__ float  g_t1[NROWS];            // row squared norms of z (transposed view)
__device__ float  g_pd[NROWS * NBLK];     // partial min distance per (row, colblock)
__device__ int    g_pi[NROWS * NBLK];     // partial argmin index per (row, colblock)
__device__ int    g_idx[NROWS];           // final argmin per row
__device__ double g_lpart[NOUTBLOCKS];    // per-block loss partial sums

__device__ __forceinline__ ull pack2(float lo, float hi) {
    ull r; asm("mov.b64 %0, {%1, %2};" : "=l"(r) : "f"(lo), "f"(hi)); return r;
}
__device__ __forceinline__ void unpack2(ull v, float& lo, float& hi) {
    asm("mov.b64 {%0, %1}, %2;" : "=f"(lo), "=f"(hi) : "l"(v));
}
// Packed dual IEEE-fp32 FMA (SASS FFMA2) — bit-identical per lane to fmaf.
__device__ __forceinline__ void fma2(ull& d, ull a, ull b) {
    asm("fma.rn.f32x2 %0, %1, %2, %0;" : "+l"(d) : "l"(a), "l"(b));
}

// ---------------------------------------------------------------------------
// K1: per-row ||z||^2. Any fp32 accumulation order is fine (lattice argument:
// only the binade of t1 matters for the rounding grid of t1 - x).
// ---------------------------------------------------------------------------
__global__ void k_prep(const float* __restrict__ z) {
    int row = blockIdx.x * blockDim.x + threadIdx.x;
    if (row >= NROWS) return;
    int b  = row >> 10;
    int hw = row & 1023;
    const float* p = z + (size_t)b * 262144 + hw;
    float s = 0.0f;
#pragma unroll 8
    for (int c = 0; c < KDIM; c++) {
        float v = p[(size_t)c * 1024];
        s = fmaf(v, v, s);
    }
    g_t1[row] = s;
}

// ---------------------------------------------------------------------------
// K2: tiled GEMM fused with per-row argmin of d = fl(t1 - fl(2*dot)).
// 128x128 tile, KT=16 k-steps, double buffered, register-staged LDG.
// 256 threads; thread (tx=tid&15, ty=tid>>4) owns rows {ty*4+il+c*64} and
// cols {tx*4+jl+c*64} (il,jl in 0..3, c in 0..1): split 4+4 chunks so smem
// reads are 2x LDS.128 per operand per k-step (full-crossbar, conflict-free).
// Accumulators packed as f32x2 row-pairs -> FFMA2 (2 FMA/issue).
// Single barrier per k-tile: compute reads `cur`, stores write `nxt`; the
// prior reads of `nxt` were fenced by the previous iteration's barrier.
// ---------------------------------------------------------------------------
__global__ void __launch_bounds__(256, 2) k_gemm(const float* __restrict__ z,
                                                 const float* __restrict__ emb) {
    __shared__ __align__(16) float As[2][KT][LDP];   // [k][m]
    __shared__ __align__(16) float Bs[2][KT][LDP];   // [k][n]

    const int tid  = threadIdx.x;
    const int tx   = tid & 15;
    const int ty   = tid >> 4;
    const int nblk = blockIdx.x;
    const int mblk = blockIdx.y;
    const int m0   = mblk * BM;
    const int n0   = nblk * BN;
    const int b    = m0 >> 10;      // all 128 rows of this block share batch b
    const int hw0  = m0 & 1023;

    const float* zb = z   + (size_t)b * 262144 + hw0;   // + k*1024 + m
    const float* eb = emb + (size_t)n0 * 256;           // + n*256  + k

    // acc2[rp][j]: rp = (c<<1)|p -> rows r0 = c*64 + ty*4 + 2p, r1 = r0+1
    // j = (c2<<2)|jl -> col c2*64 + tx*4 + jl
    ull acc2[4][8];
#pragma unroll
    for (int i = 0; i < 4; i++)
#pragma unroll
        for (int j = 0; j < 8; j++) acc2[i][j] = 0ull;

    float ra[8], rb[8];

    // --- load tile 0 ---
#pragma unroll
    for (int p = 0; p < 8; p++) {
        int idx = tid + p * 256;
        ra[p] = zb[(size_t)(idx >> 7) * 1024 + (idx & 127)];
        rb[p] = eb[(size_t)(idx >> 4) * 256 + (idx & 15)];
    }
#pragma unroll
    for (int p = 0; p < 8; p++) {
        int idx = tid + p * 256;
        As[0][idx >> 7][idx & 127] = ra[p];
        Bs[0][idx & 15][idx >> 4]  = rb[p];
    }
    __syncthreads();

    const int NKT = KDIM / KT;  // 16
#pragma unroll 1
    for (int t = 0; t < NKT; t++) {
        const int cur = t & 1;
        const int nxt = cur ^ 1;

        // issue global loads for next tile (latency hidden under compute)
        if (t + 1 < NKT) {
            const int k0 = (t + 1) * KT;
#pragma unroll
            for (int p = 0; p < 8; p++) {
                int idx = tid + p * 256;
                ra[p] = zb[(size_t)(k0 + (idx >> 7)) * 1024 + (idx & 127)];
                rb[p] = eb[(size_t)(idx >> 4) * 256 + k0 + (idx & 15)];
            }
        }

        // compute current tile
#pragma unroll 4
        for (int k = 0; k < KT; k++) {
            float4 a0 = *(const float4*)&As[cur][k][ty * 4];
            float4 a1 = *(const float4*)&As[cur][k][ty * 4 + 64];
            float4 b0 = *(const float4*)&Bs[cur][k][tx * 4];
            float4 b1 = *(const float4*)&Bs[cur][k][tx * 4 + 64];
            ull a2[4];
            a2[0] = pack2(a0.x, a0.y);
            a2[1] = pack2(a0.z, a0.w);
            a2[2] = pack2(a1.x, a1.y);
            a2[3] = pack2(a1.z, a1.w);
            ull b2[8];
            b2[0] = pack2(b0.x, b0.x);
            b2[1] = pack2(b0.y, b0.y);
            b2[2] = pack2(b0.z, b0.z);
            b2[3] = pack2(b0.w, b0.w);
            b2[4] = pack2(b1.x, b1.x);
            b2[5] = pack2(b1.y, b1.y);
            b2[6] = pack2(b1.z, b1.z);
            b2[7] = pack2(b1.w, b1.w);
#pragma unroll
            for (int rp = 0; rp < 4; rp++)
#pragma unroll
                for (int j = 0; j < 8; j++)
                    fma2(acc2[rp][j], a2[rp], b2[j]);
        }

        // stage next tile into smem (nxt buffer: no live readers this iter)
        if (t + 1 < NKT) {
#pragma unroll
            for (int p = 0; p < 8; p++) {
                int idx = tid + p * 256;
                As[nxt][idx >> 7][idx & 127] = ra[p];
                Bs[nxt][idx & 15][idx >> 4]  = rb[p];
            }
        }
        __syncthreads();
    }

    // ---- fused argmin epilogue ----
    // d = fl(t1 - fl(2*dot)); within-thread scan is ascending global col
    // (c2 chunk 0 then 1); cross-thread combine is lexicographic (d, idx),
    // which together reproduce jnp.argmin first-occurrence semantics.
    float* sd = &As[0][0][0];          // [128][16]
    int*   si = (int*)&Bs[0][0][0];    // [128][16]

#pragma unroll
    for (int rp = 0; rp < 4; rp++) {
        int r0 = (rp >> 1) * 64 + ty * 4 + (rp & 1) * 2;   // and r0+1
        float t1a = g_t1[m0 + r0];
        float t1b = g_t1[m0 + r0 + 1];
        float bda = CUDART_INF_F, bdb = CUDART_INF_F;
        int   bja = 0, bjb = 0;
#pragma unroll
        for (int j = 0; j < 8; j++) {       // ascending global col within thread
            int col = (j >> 2) * 64 + tx * 4 + (j & 3);
            float lo, hi;
            unpack2(acc2[rp][j], lo, hi);
            float da = __fsub_rn(t1a, __fmul_rn(2.0f, lo));
            float db = __fsub_rn(t1b, __fmul_rn(2.0f, hi));
            if (da < bda) { bda = da; bja = col; }
            if (db < bdb) { bdb = db; bjb = col; }
        }
        sd[r0 * 16 + tx]       = bda;
        si[r0 * 16 + tx]       = bja;
        sd[(r0 + 1) * 16 + tx] = bdb;
        si[(r0 + 1) * 16 + tx] = bjb;
    }
    __syncthreads();

    if (tid < 128) {
        float bd = CUDART_INF_F;
        int   bj = 0x7fffffff;
#pragma unroll
        for (int x = 0; x < 16; x++) {      // lexicographic: ties -> lowest col
            float d = sd[tid * 16 + x];
            int   j = si[tid * 16 + x];
            if (d < bd || (d == bd && j < bj)) { bd = d; bj = j; }
        }
        g_pd[(size_t)(m0 + tid) * NBLK + nblk] = bd;
        g_pi[(size_t)(m0 + tid) * NBLK + nblk] = n0 + bj;
    }
}

// ---------------------------------------------------------------------------
// K3: combine 128 column-block partials per row, lexicographic (d, idx) min.
// One warp per row.
// ---------------------------------------------------------------------------
__global__ void k_combine(float* __restrict__ out, int out_size) {
    int row  = blockIdx.x * 8 + (threadIdx.x >> 5);
    int lane = threadIdx.x & 31;
    if (row >= NROWS) return;

    float bd = CUDART_INF_F;
    int   bi = 0x7fffffff;
    const float* pd = g_pd + (size_t)row * NBLK;
    const int*   pi = g_pi + (size_t)row * NBLK;
#pragma unroll
    for (int x = lane; x < NBLK; x += 32) {
        float d = pd[x];
        int   i = pi[x];
        if (d < bd || (d == bd && i < bi)) { bd = d; bi = i; }
    }
#pragma unroll
    for (int o = 16; o > 0; o >>= 1) {
        float od = __shfl_down_sync(0xffffffffu, bd, o);
        int   oi = __shfl_down_sync(0xffffffffu, bi, o);
        if (od < bd || (od == bd && oi < bi)) { bd = od; bi = oi; }
    }
    if (lane == 0) {
        g_idx[row] = bi;
        int pos = NZQ + 1 + row;
        if (pos < out_size) out[pos] = (float)bi;
    }
}

// ---------------------------------------------------------------------------
// K4: z_q gather + straight-through output + per-block loss partials.
// STE emulated exactly in fp32: out = fl(z + fl(zq - z)).
// ---------------------------------------------------------------------------
__global__ void k_out(const float* __restrict__ z, const float* __restrict__ emb,
                      float* __restrict__ out, int out_size) {
    int pos = blockIdx.x * 256 + threadIdx.x;
    double contrib = 0.0;
    if (pos < NZQ) {
        int b   = pos >> 18;
        int r   = pos & 262143;
        int c   = r >> 10;
        int hw  = r & 1023;
        int row = (b << 10) + hw;
        int idx = g_idx[row];
        float ztv   = z[pos];
        float zq    = emb[(size_t)idx * 256 + c];
        float delta = __fsub_rn(zq, ztv);
        if (pos < out_size) out[pos] = __fadd_rn(ztv, delta);
        contrib = (double)__fmul_rn(delta, delta);
    }
    __shared__ double s[256];
    s[threadIdx.x] = contrib;
    __syncthreads();
#pragma unroll
    for (int o = 128; o > 0; o >>= 1) {
        if (threadIdx.x < o) s[threadIdx.x] += s[threadIdx.x + o];
        __syncthreads();
    }
    if (threadIdx.x == 0) g_lpart[blockIdx.x] = s[0];
}

// ---------------------------------------------------------------------------
// K5: deterministic final loss. loss = fl(m + fl(0.25*m)), m = fl32(sum/NZQ).
// ---------------------------------------------------------------------------
__global__ void k_loss(float* __restrict__ out, int out_size) {
    __shared__ double s[256];
    double acc = 0.0;
    for (int x = threadIdx.x; x < NOUTBLOCKS; x += 256) acc += g_lpart[x];
    s[threadIdx.x] = acc;
    __syncthreads();
#pragma unroll
    for (int o = 128; o > 0; o >>= 1) {
        if (threadIdx.x < o) s[threadIdx.x] += s[threadIdx.x + o];
        __syncthreads();
    }
    if (threadIdx.x == 0 && NZQ < out_size) {
        float m = (float)(s[0] / (double)NZQ);
        out[NZQ] = __fadd_rn(m, __fmul_rn(0.25f, m));
    }
}

// ---------------------------------------------------------------------------
extern "C" void kernel_launch(void* const* d_in, const int* in_sizes, int n_in,
                              void* d_out, int out_size) {
    const float* z   = (const float*)d_in[0];   // [8,256,32,32]
    const float* emb = (const float*)d_in[1];   // [16384,256]
    float* out = (float*)d_out;

    k_prep<<<NROWS / 256, 256>>>(z);

    dim3 grid(NBLK, MBLK);
    k_gemm<<<grid, 256>>>(z, emb);

    k_combine<<<NROWS / 8, 256>>>(out, out_size);
    k_out<<<NOUTBLOCKS, 256>>>(z, emb, out, out_size);
    k_loss<<<1, 256>>>(out, out_size);
}

// round 10
// speedup vs baseline: 1.6796x; 1.0196x over previous
#include <cuda_runtime.h>
#include <cuda_bf16.h>
#include <math_constants.h>
#include <cstdint>

// Problem constants
#define NROWS 8192      // B*H*W = 8*32*32
#define NE    16384
#define KDIM  256
#define KEXT  1536      // 6 split-pairs * 256
#define NCHUNK 24       // KEXT/64
#define TCM   128       // rows per CTA tile
#define TCN   256       // cols per CTA tile
#define NBLK2 (NE / TCN)    // 64
#define MBLK2 (NROWS / TCM) // 64
#define NZQ   2097152
#define NOUTBLOCKS (NZQ / 256)
#define RESCREEN_THR 1e-4f   // > 2 lattice steps (6.1e-5): captures all exact achievers

#define SWZ(x) ((x) ^ (((x) >> 3) & 0x70))

// GEMM smem: A chunks (128 rows x 128B) x2, B chunks (256 rows x 128B) x2
#define SMA0 0
#define SMA1 16384
#define SMB0 32768
#define SMB1 65536
#define SM_TOTAL 98304

// Scratch (device globals; no allocation allowed)
__device__ float  g_t1[NROWS];
__device__ float  g_pd[NROWS * 64];
__device__ int    g_pi[NROWS * 64];
__device__ float  g_md[NROWS];            // global TC-min per row
__device__ int    g_idx[NROWS];
__device__ double g_lpart[NOUTBLOCKS];
__device__ __align__(16) __nv_bfloat16 g_Aext[(size_t)NROWS * KEXT];   // 24 MB
__device__ __align__(16) __nv_bfloat16 g_Bext[(size_t)NE * KEXT];      // 48 MB
__device__ __align__(16) float g_D[(size_t)NROWS * NE];                // 512 MB TC d values

// ---------------- PTX helpers (all baseline ISA, legal on plain sm_100) ----
__device__ __forceinline__ uint32_t smem_u32(const void* p) {
    uint32_t a;
    asm("{ .reg .u64 t; cvta.to.shared.u64 t, %1; cvt.u32.u64 %0, t; }" : "=r"(a) : "l"(p));
    return a;
}
__device__ __forceinline__ void cp16(uint32_t d, const void* s) {
    asm volatile("cp.async.cg.shared.global [%0], [%1], 16;" :: "r"(d), "l"(s) : "memory");
}
__device__ __forceinline__ void ldm_x4(uint32_t* r, uint32_t a) {
    asm volatile("ldmatrix.sync.aligned.m8n8.x4.shared.b16 {%0,%1,%2,%3}, [%4];"
                 : "=r"(r[0]), "=r"(r[1]), "=r"(r[2]), "=r"(r[3]) : "r"(a));
}
__device__ __forceinline__ void mma16816(float* c, const uint32_t* a,
                                         uint32_t b0, uint32_t b1) {
    asm volatile(
        "mma.sync.aligned.m16n8k16.row.col.f32.bf16.bf16.f32 "
        "{%0,%1,%2,%3}, {%4,%5,%6,%7}, {%8,%9}, {%0,%1,%2,%3};"
        : "+f"(c[0]), "+f"(c[1]), "+f"(c[2]), "+f"(c[3])
        : "r"(a[0]), "r"(a[1]), "r"(a[2]), "r"(a[3]), "r"(b0), "r"(b1));
}

// Exact RZ 3-way bf16 split: x == s0 + s1 + s2 exactly.
__device__ __forceinline__ void split3(float x, __nv_bfloat16& s0,
                                       __nv_bfloat16& s1, __nv_bfloat16& s2) {
    s0 = __float2bfloat16_rz(x);
    float r1 = __fsub_rn(x, __bfloat162float(s0));     // exact (Sterbenz)
    s1 = __float2bfloat16_rz(r1);
    float r2 = __fsub_rn(r1, __bfloat162float(s1));    // exact
    s2 = __float2bfloat16_rz(r2);                      // == r2 exactly
}

// ---------------------------------------------------------------------------
// K1: per-row ||z||^2.
// ---------------------------------------------------------------------------
__global__ void k_prep(const float* __restrict__ z) {
    int row = blockIdx.x * blockDim.x + threadIdx.x;
    if (row >= NROWS) return;
    int b  = row >> 10;
    int hw = row & 1023;
    const float* p = z + (size_t)b * 262144 + hw;
    float s = 0.0f;
#pragma unroll 8
    for (int c = 0; c < KDIM; c++) {
        float v = p[(size_t)c * 1024];
        s = fmaf(v, v, s);
    }
    g_t1[row] = s;
}

// ---------------------------------------------------------------------------
// K1b: split emb into B_ext. b-split order {0,1,0,1,2,0}
// (paired with a-split {0,0,1,1,0,2}): products z0e0,z0e1,z1e0,z1e1,z0e2,z2e0.
// ---------------------------------------------------------------------------
__global__ void k_splitB(const float* __restrict__ emb) {
    int t = blockIdx.x * 256 + threadIdx.x;
    if (t >= NE * KDIM) return;
    int n = t >> 8, k = t & 255;
    __nv_bfloat16 e0, e1, e2;
    split3(emb[(size_t)n * 256 + k], e0, e1, e2);
    __nv_bfloat16* d = g_Bext + (size_t)n * KEXT + k;
    d[0]    = e0;
    d[256]  = e1;
    d[512]  = e0;
    d[768]  = e1;
    d[1024] = e2;
    d[1280] = e0;
}

// ---------------------------------------------------------------------------
// K1c: split z (transposed view) into A_ext. a-split order {0,0,1,1,0,2}.
// ---------------------------------------------------------------------------
__global__ void k_splitA(const float* __restrict__ z) {
    __shared__ float s[32][33];
    int tx = threadIdx.x & 31, ty = threadIdx.x >> 5;
    int hw0 = blockIdx.x * 32, c0 = blockIdx.y * 32, b = blockIdx.z;
    s[ty][tx] = z[(size_t)b * 262144 + (size_t)(c0 + ty) * 1024 + hw0 + tx];
    __syncthreads();
    int r = (b << 10) + hw0 + ty;
    int c = c0 + tx;
    __nv_bfloat16 z0, z1, z2;
    split3(s[tx][ty], z0, z1, z2);
    __nv_bfloat16* d = g_Aext + (size_t)r * KEXT + c;
    d[0]    = z0;
    d[256]  = z0;
    d[512]  = z1;
    d[768]  = z1;
    d[1024] = z0;
    d[1280] = z2;
}

// ---------------------------------------------------------------------------
// K2: mma.sync bf16 GEMM (dot over KEXT=1536), screening pass.
// CTA 128x256, 512 threads = 16 warps (4m x 4n), warp tile 32x64.
// Epilogue: stores ALL d_tc values to g_D (for rescreen) + per-colblock min.
// ---------------------------------------------------------------------------
__global__ void __launch_bounds__(512, 1) k_gemm_mma() {
    extern __shared__ char smem[];
    const uint32_t sb = smem_u32(smem);
    const int tid  = threadIdx.x;
    const int lane = tid & 31;
    const int warp = tid >> 5;
    const int wm   = warp >> 2;         // 0..3: m block of 32
    const int wn   = warp & 3;          // 0..3: n block of 64
    const int q    = lane >> 2;         // quad id 0..7
    const int qt   = lane & 3;
    const int nb   = blockIdx.x;
    const int mb   = blockIdx.y;
    const int m0   = mb * TCM;
    const int n0   = nb * TCN;

    const char* Ag = (const char*)(g_Aext + (size_t)m0 * KEXT);
    const char* Bg = (const char*)(g_Bext + (size_t)n0 * KEXT);

    // ldmatrix lane address patterns
    const int a_r  = (lane & 7) + ((lane >> 3) & 1) * 8;   // row within m16
    const int a_kh = lane >> 4;                            // k-half
    const int b_r  = (lane & 7) + ((lane >> 4) & 1) * 8;   // row within n16 pair
    const int b_kh = (lane >> 3) & 1;                      // k-half

    float acc[2][8][4];
#pragma unroll
    for (int mt = 0; mt < 2; mt++)
#pragma unroll
        for (int nt = 0; nt < 8; nt++)
#pragma unroll
            for (int r = 0; r < 4; r++) acc[mt][nt][r] = 0.0f;

    auto load_chunk = [&](int ck, int buf) {
        const int koff = ck * 128;
#pragma unroll
        for (int p = 0; p < 2; p++) {
            int idx = tid + p * 512;
            int row = idx >> 3, g = idx & 7;
            cp16(sb + (buf ? SMA1 : SMA0) + (uint32_t)SWZ(row * 128 + g * 16),
                 Ag + (size_t)row * 3072 + koff + g * 16);
        }
#pragma unroll
        for (int p = 0; p < 4; p++) {
            int idx = tid + p * 512;
            int row = idx >> 3, g = idx & 7;
            cp16(sb + (buf ? SMB1 : SMB0) + (uint32_t)SWZ(row * 128 + g * 16),
                 Bg + (size_t)row * 3072 + koff + g * 16);
        }
    };

    load_chunk(0, 0);
    asm volatile("cp.async.commit_group;" ::: "memory");
    asm volatile("cp.async.wait_group 0;" ::: "memory");
    __syncthreads();

#pragma unroll 1
    for (int ck = 0; ck < NCHUNK; ck++) {
        const int cur = ck & 1;
        if (ck + 1 < NCHUNK) {
            load_chunk(ck + 1, cur ^ 1);
            asm volatile("cp.async.commit_group;" ::: "memory");
        }
        const uint32_t sA = sb + (cur ? SMA1 : SMA0);
        const uint32_t sB = sb + (cur ? SMB1 : SMB0);

#pragma unroll
        for (int kk = 0; kk < 4; kk++) {
            uint32_t a[2][4];
#pragma unroll
            for (int mt = 0; mt < 2; mt++) {
                int row  = wm * 32 + mt * 16 + a_r;
                int byte = row * 128 + (kk * 2 + a_kh) * 16;
                ldm_x4(a[mt], sA + (byte ^ ((byte >> 3) & 0x70)));
            }
#pragma unroll
            for (int ntp = 0; ntp < 4; ntp++) {
                int row  = wn * 64 + ntp * 16 + b_r;
                int byte = row * 128 + (kk * 2 + b_kh) * 16;
                uint32_t bbf[4];
                ldm_x4(bbf, sB + (byte ^ ((byte >> 3) & 0x70)));
#pragma unroll
                for (int mt = 0; mt < 2; mt++) {
                    mma16816(acc[mt][2 * ntp],     a[mt], bbf[0], bbf[1]);
                    mma16816(acc[mt][2 * ntp + 1], a[mt], bbf[2], bbf[3]);
                }
            }
        }
        if (ck + 1 < NCHUNK)
            asm volatile("cp.async.wait_group 0;" ::: "memory");
        __syncthreads();
    }

    // ---- epilogue: store d_tc matrix + per-colblock screening min ----
    float* sd = (float*)smem;            // [128][4]
    int*   si = (int*)(smem + 2048);     // [128][4]

#pragma unroll
    for (int s = 0; s < 4; s++) {
        const int mt = s >> 1;
        const int ch = (s & 1) * 2;                 // c-reg pair: rows q / q+8
        const int rl = wm * 32 + mt * 16 + (s & 1) * 8 + q;
        const float t1 = g_t1[m0 + rl];
        float bd = CUDART_INF_F;
        int   bi = 0;
        float* drow = g_D + (size_t)(m0 + rl) * NE + n0;
#pragma unroll
        for (int nt = 0; nt < 8; nt++) {
            int c0 = wn * 64 + nt * 8 + qt * 2;
            float d0 = __fsub_rn(t1, __fmul_rn(2.0f, acc[mt][nt][ch]));
            float d1 = __fsub_rn(t1, __fmul_rn(2.0f, acc[mt][nt][ch + 1]));
            *(float2*)&drow[c0] = make_float2(d0, d1);   // full 32B sectors
            if (d0 < bd) { bd = d0; bi = c0; }
            if (d1 < bd) { bd = d1; bi = c0 + 1; }
        }
#pragma unroll
        for (int o = 1; o <= 2; o <<= 1) {
            float od = __shfl_xor_sync(0xffffffffu, bd, o);
            int   oi = __shfl_xor_sync(0xffffffffu, bi, o);
            if (od < bd || (od == bd && oi < bi)) { bd = od; bi = oi; }
        }
        if (qt == 0) { sd[rl * 4 + wn] = bd; si[rl * 4 + wn] = bi; }
    }
    __syncthreads();

    if (tid < 128) {
        float bd = CUDART_INF_F;
        int   bi = 0x7fffffff;
#pragma unroll
        for (int w = 0; w < 4; w++) {
            float d = sd[tid * 4 + w];
            int   i = si[tid * 4 + w];
            if (d < bd || (d == bd && i < bi)) { bd = d; bi = i; }
        }
        g_pd[(size_t)(m0 + tid) * NBLK2 + nb] = bd;
        g_pi[(size_t)(m0 + tid) * NBLK2 + nb] = n0 + bi;
    }
}

// ---------------------------------------------------------------------------
// K3: global TC-min per row (screening threshold base).
// ---------------------------------------------------------------------------
__global__ void k_combine() {
    int row  = blockIdx.x * 8 + (threadIdx.x >> 5);
    int lane = threadIdx.x & 31;
    if (row >= NROWS) return;

    float bd = CUDART_INF_F;
    const float* pd = g_pd + (size_t)row * NBLK2;
#pragma unroll
    for (int x = lane; x < NBLK2; x += 32) {
        float d = pd[x];
        if (d < bd) bd = d;
    }
#pragma unroll
    for (int o = 16; o > 0; o >>= 1) {
        float od = __shfl_down_sync(0xffffffffu, bd, o);
        if (od < bd) bd = od;
    }
    if (lane == 0) g_md[row] = bd;
}

// ---------------------------------------------------------------------------
// K3b: rescreen. For candidates with d_tc <= m_tc + THR (THR > 2 lattice
// steps, so every exact achiever is captured: d_tc deviates <= 1 step from
// exact), recompute d exactly in fp32 (sequential fmaf, validated class) and
// take lexicographic (d, idx) min = jnp.argmin first-occurrence.
// One block (256 threads) per row; g_D row scan is coalesced.
// ---------------------------------------------------------------------------
__global__ void k_rescreen(const float* __restrict__ z,
                           const float* __restrict__ emb,
                           float* __restrict__ out, int out_size) {
    __shared__ float zr[KDIM];
    __shared__ float sbd[256];
    __shared__ int   sbi[256];
    const int row = blockIdx.x;
    const int tid = threadIdx.x;
    const int b = row >> 10, hw = row & 1023;
    zr[tid] = z[(size_t)b * 262144 + (size_t)tid * 1024 + hw];
    __syncthreads();

    const float t1  = g_t1[row];
    const float thr = g_md[row] + RESCREEN_THR;
    const float* drow = g_D + (size_t)row * NE;

    float bd = CUDART_INF_F;
    int   bi = 0x7fffffff;
#pragma unroll 1
    for (int col = tid; col < NE; col += 256) {
        if (drow[col] <= thr) {
            const float* e = emb + (size_t)col * KDIM;
            float s = 0.0f;
#pragma unroll 8
            for (int k = 0; k < KDIM; k++) s = fmaf(zr[k], e[k], s);
            float dex = __fsub_rn(t1, __fmul_rn(2.0f, s));
            if (dex < bd || (dex == bd && col < bi)) { bd = dex; bi = col; }
        }
    }
    sbd[tid] = bd; sbi[tid] = bi;
    __syncthreads();
#pragma unroll
    for (int o = 128; o > 0; o >>= 1) {
        if (tid < o) {
            float od = sbd[tid + o]; int oi = sbi[tid + o];
            if (od < sbd[tid] || (od == sbd[tid] && oi < sbi[tid])) {
                sbd[tid] = od; sbi[tid] = oi;
            }
        }
        __syncthreads();
    }
    if (tid == 0) {
        g_idx[row] = sbi[0];
        int pos = NZQ + 1 + row;
        if (pos < out_size) out[pos] = (float)sbi[0];
    }
}

// ---------------------------------------------------------------------------
// K4: z_q gather + STE output + per-block loss partials (exact fp32 emulation).
// ---------------------------------------------------------------------------
__global__ void k_out(const float* __restrict__ z, const float* __restrict__ emb,
                      float* __restrict__ out, int out_size) {
    int pos = blockIdx.x * 256 + threadIdx.x;
    double contrib = 0.0;
    if (pos < NZQ) {
        int b   = pos >> 18;
        int r   = pos & 262143;
        int c   = r >> 10;
        int hw  = r & 1023;
        int row = (b << 10) + hw;
        int idx = g_idx[row];
        float ztv   = z[pos];
        float zq    = emb[(size_t)idx * 256 + c];
        float delta = __fsub_rn(zq, ztv);
        if (pos < out_size) out[pos] = __fadd_rn(ztv, delta);
        contrib = (double)__fmul_rn(delta, delta);
    }
    __shared__ double s[256];
    s[threadIdx.x] = contrib;
    __syncthreads();
#pragma unroll
    for (int o = 128; o > 0; o >>= 1) {
        if (threadIdx.x < o) s[threadIdx.x] += s[threadIdx.x + o];
        __syncthreads();
    }
    if (threadIdx.x == 0) g_lpart[blockIdx.x] = s[0];
}

// ---------------------------------------------------------------------------
// K5: deterministic final loss. loss = fl(m + fl(0.25*m)), m = fl32(sum/NZQ).
// ---------------------------------------------------------------------------
__global__ void k_loss(float* __restrict__ out, int out_size) {
    __shared__ double s[256];
    double acc = 0.0;
    for (int x = threadIdx.x; x < NOUTBLOCKS; x += 256) acc += g_lpart[x];
    s[threadIdx.x] = acc;
    __syncthreads();
#pragma unroll
    for (int o = 128; o > 0; o >>= 1) {
        if (threadIdx.x < o) s[threadIdx.x] += s[threadIdx.x + o];
        __syncthreads();
    }
    if (threadIdx.x == 0 && NZQ < out_size) {
        float m = (float)(s[0] / (double)NZQ);
        out[NZQ] = __fadd_rn(m, __fmul_rn(0.25f, m));
    }
}

// ---------------------------------------------------------------------------
extern "C" void kernel_launch(void* const* d_in, const int* in_sizes, int n_in,
                              void* d_out, int out_size) {
    const float* z   = (const float*)d_in[0];   // [8,256,32,32]
    const float* emb = (const float*)d_in[1];   // [16384,256]
    float* out = (float*)d_out;

    cudaFuncSetAttribute(k_gemm_mma, cudaFuncAttributeMaxDynamicSharedMemorySize,
                         SM_TOTAL);

    k_prep<<<NROWS / 256, 256>>>(z);
    k_splitB<<<(NE * KDIM) / 256, 256>>>(emb);
    {
        dim3 g(32, 8, 8);   // hw-tiles, c-tiles, b
        k_splitA<<<g, dim3(32 * 32)>>>(z);
    }
    {
        dim3 g(NBLK2, MBLK2);   // 64 x 64
        k_gemm_mma<<<g, 512, SM_TOTAL>>>();
    }
    k_combine<<<NROWS / 8, 256>>>();
    k_rescreen<<<NROWS, 256>>>(z, emb, out, out_size);
    k_out<<<NOUTBLOCKS, 256>>>(z, emb, out, out_size);
    k_loss<<<1, 256>>>(out, out_size);
}

// round 11
// speedup vs baseline: 3.2020x; 1.9064x over previous
#include <cuda_runtime.h>
#include <cuda_bf16.h>
#include <math_constants.h>
#include <cstdint>

// Problem constants
#define NROWS 8192      // B*H*W = 8*32*32
#define NE    16384
#define KDIM  256
#define NCHUNK 4        // KDIM/64
#define TCM   128       // rows per CTA tile
#define TCN   256       // cols per CTA tile
#define NBLK2 (NE / TCN)    // 64
#define MBLK2 (NROWS / TCM) // 64
#define NZQ   2097152
#define NOUTBLOCKS (NZQ / 256)
// Screening threshold: provable worst-case bf16 screening deviation
// delta_d <= 2 * 2^-7 * ||z|| * ||e|| <= 1.4e-4; THR > 2*delta (capture proof)
#define RESCREEN_THR 6e-4f

#define SWZ(x) ((x) ^ (((x) >> 3) & 0x70))

// GEMM smem: A chunks (128 rows x 128B) x2, B chunks (256 rows x 128B) x2
#define SMA0 0
#define SMA1 16384
#define SMB0 32768
#define SMB1 65536
#define SM_TOTAL 98304

// Scratch (device globals; no allocation allowed)
__device__ float  g_t1[NROWS];
__device__ float  g_pd[NROWS * 64];
__device__ float  g_md[NROWS];            // global TC-min per row
__device__ int    g_idx[NROWS];
__device__ double g_lpart[NOUTBLOCKS];
__device__ __align__(16) __nv_bfloat16 g_Aext[(size_t)NROWS * KDIM];   // 4 MB
__device__ __align__(16) __nv_bfloat16 g_Bext[(size_t)NE * KDIM];      // 8 MB
__device__ __align__(16) float g_D[(size_t)NROWS * NE];                // 512 MB TC d values

// ---------------- PTX helpers (all baseline ISA, legal on plain sm_100) ----
__device__ __forceinline__ uint32_t smem_u32(const void* p) {
    uint32_t a;
    asm("{ .reg .u64 t; cvta.to.shared.u64 t, %1; cvt.u32.u64 %0, t; }" : "=r"(a) : "l"(p));
    return a;
}
__device__ __forceinline__ void cp16(uint32_t d, const void* s) {
    asm volatile("cp.async.cg.shared.global [%0], [%1], 16;" :: "r"(d), "l"(s) : "memory");
}
__device__ __forceinline__ void ldm_x4(uint32_t* r, uint32_t a) {
    asm volatile("ldmatrix.sync.aligned.m8n8.x4.shared.b16 {%0,%1,%2,%3}, [%4];"
                 : "=r"(r[0]), "=r"(r[1]), "=r"(r[2]), "=r"(r[3]) : "r"(a));
}
__device__ __forceinline__ void mma16816(float* c, const uint32_t* a,
                                         uint32_t b0, uint32_t b1) {
    asm volatile(
        "mma.sync.aligned.m16n8k16.row.col.f32.bf16.bf16.f32 "
        "{%0,%1,%2,%3}, {%4,%5,%6,%7}, {%8,%9}, {%0,%1,%2,%3};"
        : "+f"(c[0]), "+f"(c[1]), "+f"(c[2]), "+f"(c[3])
        : "r"(a[0]), "r"(a[1]), "r"(a[2]), "r"(a[3]), "r"(b0), "r"(b1));
}

// ---------------------------------------------------------------------------
// K1: per-row ||z||^2.
// ---------------------------------------------------------------------------
__global__ void k_prep(const float* __restrict__ z) {
    int row = blockIdx.x * blockDim.x + threadIdx.x;
    if (row >= NROWS) return;
    int b  = row >> 10;
    int hw = row & 1023;
    const float* p = z + (size_t)b * 262144 + hw;
    float s = 0.0f;
#pragma unroll 8
    for (int c = 0; c < KDIM; c++) {
        float v = p[(size_t)c * 1024];
        s = fmaf(v, v, s);
    }
    g_t1[row] = s;
}

// ---------------------------------------------------------------------------
// K1b: RN-convert emb to bf16 (screening precision only; rescreen repairs).
// ---------------------------------------------------------------------------
__global__ void k_convB(const float* __restrict__ emb) {
    int t = blockIdx.x * 256 + threadIdx.x;
    if (t >= NE * KDIM) return;
    g_Bext[t] = __float2bfloat16(emb[t]);
}

// ---------------------------------------------------------------------------
// K1c: transpose z to row-major [row][k] and RN-convert to bf16.
// ---------------------------------------------------------------------------
__global__ void k_convA(const float* __restrict__ z) {
    __shared__ float s[32][33];
    int tx = threadIdx.x & 31, ty = threadIdx.x >> 5;
    int hw0 = blockIdx.x * 32, c0 = blockIdx.y * 32, b = blockIdx.z;
    s[ty][tx] = z[(size_t)b * 262144 + (size_t)(c0 + ty) * 1024 + hw0 + tx];
    __syncthreads();
    int r = (b << 10) + hw0 + ty;
    int c = c0 + tx;
    g_Aext[(size_t)r * KDIM + c] = __float2bfloat16(s[tx][ty]);
}

// ---------------------------------------------------------------------------
// K2: mma.sync bf16 GEMM (dot over K=256), screening pass.
// CTA 128x256, 512 threads = 16 warps (4m x 4n), warp tile 32x64.
// 4 K-chunks of 64 bf16 (=128B SW128 rows), cp.async double buffered.
// Epilogue: stores ALL d_tc values to g_D (for rescreen) + per-colblock min.
// ---------------------------------------------------------------------------
__global__ void __launch_bounds__(512, 1) k_gemm_mma() {
    extern __shared__ char smem[];
    const uint32_t sb = smem_u32(smem);
    const int tid  = threadIdx.x;
    const int lane = tid & 31;
    const int warp = tid >> 5;
    const int wm   = warp >> 2;         // 0..3: m block of 32
    const int wn   = warp & 3;          // 0..3: n block of 64
    const int q    = lane >> 2;         // quad id 0..7
    const int qt   = lane & 3;
    const int nb   = blockIdx.x;
    const int mb   = blockIdx.y;
    const int m0   = mb * TCM;
    const int n0   = nb * TCN;

    const char* Ag = (const char*)(g_Aext + (size_t)m0 * KDIM);
    const char* Bg = (const char*)(g_Bext + (size_t)n0 * KDIM);

    // ldmatrix lane address patterns
    const int a_r  = (lane & 7) + ((lane >> 3) & 1) * 8;   // row within m16
    const int a_kh = lane >> 4;                            // k-half
    const int b_r  = (lane & 7) + ((lane >> 4) & 1) * 8;   // row within n16 pair
    const int b_kh = (lane >> 3) & 1;                      // k-half

    float acc[2][8][4];
#pragma unroll
    for (int mt = 0; mt < 2; mt++)
#pragma unroll
        for (int nt = 0; nt < 8; nt++)
#pragma unroll
            for (int r = 0; r < 4; r++) acc[mt][nt][r] = 0.0f;

    // chunk loader: row stride is KDIM*2 = 512 bytes
    auto load_chunk = [&](int ck, int buf) {
        const int koff = ck * 128;
#pragma unroll
        for (int p = 0; p < 2; p++) {
            int idx = tid + p * 512;
            int row = idx >> 3, g = idx & 7;
            cp16(sb + (buf ? SMA1 : SMA0) + (uint32_t)SWZ(row * 128 + g * 16),
                 Ag + (size_t)row * 512 + koff + g * 16);
        }
#pragma unroll
        for (int p = 0; p < 4; p++) {
            int idx = tid + p * 512;
            int row = idx >> 3, g = idx & 7;
            cp16(sb + (buf ? SMB1 : SMB0) + (uint32_t)SWZ(row * 128 + g * 16),
                 Bg + (size_t)row * 512 + koff + g * 16);
        }
    };

    load_chunk(0, 0);
    asm volatile("cp.async.commit_group;" ::: "memory");
    asm volatile("cp.async.wait_group 0;" ::: "memory");
    __syncthreads();

#pragma unroll 1
    for (int ck = 0; ck < NCHUNK; ck++) {
        const int cur = ck & 1;
        if (ck + 1 < NCHUNK) {
            load_chunk(ck + 1, cur ^ 1);
            asm volatile("cp.async.commit_group;" ::: "memory");
        }
        const uint32_t sA = sb + (cur ? SMA1 : SMA0);
        const uint32_t sB = sb + (cur ? SMB1 : SMB0);

#pragma unroll
        for (int kk = 0; kk < 4; kk++) {
            uint32_t a[2][4];
#pragma unroll
            for (int mt = 0; mt < 2; mt++) {
                int row  = wm * 32 + mt * 16 + a_r;
                int byte = row * 128 + (kk * 2 + a_kh) * 16;
                ldm_x4(a[mt], sA + (byte ^ ((byte >> 3) & 0x70)));
            }
#pragma unroll
            for (int ntp = 0; ntp < 4; ntp++) {
                int row  = wn * 64 + ntp * 16 + b_r;
                int byte = row * 128 + (kk * 2 + b_kh) * 16;
                uint32_t bbf[4];
                ldm_x4(bbf, sB + (byte ^ ((byte >> 3) & 0x70)));
#pragma unroll
                for (int mt = 0; mt < 2; mt++) {
                    mma16816(acc[mt][2 * ntp],     a[mt], bbf[0], bbf[1]);
                    mma16816(acc[mt][2 * ntp + 1], a[mt], bbf[2], bbf[3]);
                }
            }
        }
        if (ck + 1 < NCHUNK)
            asm volatile("cp.async.wait_group 0;" ::: "memory");
        __syncthreads();
    }

    // ---- epilogue: store d_tc matrix + per-colblock screening min ----
    float* sd = (float*)smem;            // [128][4]

#pragma unroll
    for (int s = 0; s < 4; s++) {
        const int mt = s >> 1;
        const int ch = (s & 1) * 2;                 // c-reg pair: rows q / q+8
        const int rl = wm * 32 + mt * 16 + (s & 1) * 8 + q;
        const float t1 = g_t1[m0 + rl];
        float bd = CUDART_INF_F;
        float* drow = g_D + (size_t)(m0 + rl) * NE + n0;
#pragma unroll
        for (int nt = 0; nt < 8; nt++) {
            int c0 = wn * 64 + nt * 8 + qt * 2;
            float d0 = __fsub_rn(t1, __fmul_rn(2.0f, acc[mt][nt][ch]));
            float d1 = __fsub_rn(t1, __fmul_rn(2.0f, acc[mt][nt][ch + 1]));
            *(float2*)&drow[c0] = make_float2(d0, d1);   // full 32B sectors
            bd = fminf(bd, fminf(d0, d1));
        }
#pragma unroll
        for (int o = 1; o <= 2; o <<= 1) {
            float od = __shfl_xor_sync(0xffffffffu, bd, o);
            bd = fminf(bd, od);
        }
        if (qt == 0) sd[rl * 4 + wn] = bd;
    }
    __syncthreads();

    if (tid < 128) {
        float bd = CUDART_INF_F;
#pragma unroll
        for (int w = 0; w < 4; w++) bd = fminf(bd, sd[tid * 4 + w]);
        g_pd[(size_t)(m0 + tid) * NBLK2 + nb] = bd;
    }
}

// ---------------------------------------------------------------------------
// K3: global TC-min per row (screening threshold base).
// ---------------------------------------------------------------------------
__global__ void k_combine() {
    int row  = blockIdx.x * 8 + (threadIdx.x >> 5);
    int lane = threadIdx.x & 31;
    if (row >= NROWS) return;

    float bd = CUDART_INF_F;
    const float* pd = g_pd + (size_t)row * NBLK2;
#pragma unroll
    for (int x = lane; x < NBLK2; x += 32) bd = fminf(bd, pd[x]);
#pragma unroll
    for (int o = 16; o > 0; o >>= 1)
        bd = fminf(bd, __shfl_down_sync(0xffffffffu, bd, o));
    if (lane == 0) g_md[row] = bd;
}

// ---------------------------------------------------------------------------
// K3b: rescreen. |d_tc - d_exact| <= 1.4e-4 provably (Cauchy-Schwarz bf16
// bound), THR = 6e-4 > 2*delta: every exact achiever has d_tc <= m_tc + THR.
// Recompute exact fp32 d for candidates, lexicographic (d, idx) min =
// jnp.argmin first-occurrence. One block (256 threads) per row.
// ---------------------------------------------------------------------------
__global__ void k_rescreen(const float* __restrict__ z,
                           const float* __restrict__ emb,
                           float* __restrict__ out, int out_size) {
    __shared__ float zr[KDIM];
    __shared__ float sbd[256];
    __shared__ int   sbi[256];
    const int row = blockIdx.x;
    const int tid = threadIdx.x;
    const int b = row >> 10, hw = row & 1023;
    zr[tid] = z[(size_t)b * 262144 + (size_t)tid * 1024 + hw];
    __syncthreads();

    const float t1  = g_t1[row];
    const float thr = g_md[row] + RESCREEN_THR;
    const float* drow = g_D + (size_t)row * NE;

    float bd = CUDART_INF_F;
    int   bi = 0x7fffffff;
#pragma unroll 1
    for (int col = tid; col < NE; col += 256) {
        if (drow[col] <= thr) {
            const float* e = emb + (size_t)col * KDIM;
            float s = 0.0f;
#pragma unroll 8
            for (int k = 0; k < KDIM; k++) s = fmaf(zr[k], e[k], s);
            float dex = __fsub_rn(t1, __fmul_rn(2.0f, s));
            if (dex < bd || (dex == bd && col < bi)) { bd = dex; bi = col; }
        }
    }
    sbd[tid] = bd; sbi[tid] = bi;
    __syncthreads();
#pragma unroll
    for (int o = 128; o > 0; o >>= 1) {
        if (tid < o) {
            float od = sbd[tid + o]; int oi = sbi[tid + o];
            if (od < sbd[tid] || (od == sbd[tid] && oi < sbi[tid])) {
                sbd[tid] = od; sbi[tid] = oi;
            }
        }
        __syncthreads();
    }
    if (tid == 0) {
        g_idx[row] = sbi[0];
        int pos = NZQ + 1 + row;
        if (pos < out_size) out[pos] = (float)sbi[0];
    }
}

// ---------------------------------------------------------------------------
// K4: z_q gather + STE output + per-block loss partials (exact fp32 emulation).
// ---------------------------------------------------------------------------
__global__ void k_out(const float* __restrict__ z, const float* __restrict__ emb,
                      float* __restrict__ out, int out_size) {
    int pos = blockIdx.x * 256 + threadIdx.x;
    double contrib = 0.0;
    if (pos < NZQ) {
        int b   = pos >> 18;
        int r   = pos & 262143;
        int c   = r >> 10;
        int hw  = r & 1023;
        int row = (b << 10) + hw;
        int idx = g_idx[row];
        float ztv   = z[pos];
        float zq    = emb[(size_t)idx * 256 + c];
        float delta = __fsub_rn(zq, ztv);
        if (pos < out_size) out[pos] = __fadd_rn(ztv, delta);
        contrib = (double)__fmul_rn(delta, delta);
    }
    __shared__ double s[256];
    s[threadIdx.x] = contrib;
    __syncthreads();
#pragma unroll
    for (int o = 128; o > 0; o >>= 1) {
        if (threadIdx.x < o) s[threadIdx.x] += s[threadIdx.x + o];
        __syncthreads();
    }
    if (threadIdx.x == 0) g_lpart[blockIdx.x] = s[0];
}

// ---------------------------------------------------------------------------
// K5: deterministic final loss. loss = fl(m + fl(0.25*m)), m = fl32(sum/NZQ).
// ---------------------------------------------------------------------------
__global__ void k_loss(float* __restrict__ out, int out_size) {
    __shared__ double s[256];
    double acc = 0.0;
    for (int x = threadIdx.x; x < NOUTBLOCKS; x += 256) acc += g_lpart[x];
    s[threadIdx.x] = acc;
    __syncthreads();
#pragma unroll
    for (int o = 128; o > 0; o >>= 1) {
        if (threadIdx.x < o) s[threadIdx.x] += s[threadIdx.x + o];
        __syncthreads();
    }
    if (threadIdx.x == 0 && NZQ < out_size) {
        float m = (float)(s[0] / (double)NZQ);
        out[NZQ] = __fadd_rn(m, __fmul_rn(0.25f, m));
    }
}

// ---------------------------------------------------------------------------
extern "C" void kernel_launch(void* const* d_in, const int* in_sizes, int n_in,
                              void* d_out, int out_size) {
    const float* z   = (const float*)d_in[0];   // [8,256,32,32]
    const float* emb = (const float*)d_in[1];   // [16384,256]
    float* out = (float*)d_out;

    cudaFuncSetAttribute(k_gemm_mma, cudaFuncAttributeMaxDynamicSharedMemorySize,
                         SM_TOTAL);

    k_prep<<<NROWS / 256, 256>>>(z);
    k_convB<<<(NE * KDIM) / 256, 256>>>(emb);
    {
        dim3 g(32, 8, 8);   // hw-tiles, c-tiles, b
        k_convA<<<g, dim3(32 * 32)>>>(z);
    }
    {
        dim3 g(NBLK2, MBLK2);   // 64 x 64
        k_gemm_mma<<<g, 512, SM_TOTAL>>>();
    }
    k_combine<<<NROWS / 8, 256>>>();
    k_rescreen<<<NROWS, 256>>>(z, emb, out, out_size);
    k_out<<<NOUTBLOCKS, 256>>>(z, emb, out, out_size);
    k_loss<<<1, 256>>>(out, out_size);
}

// round 12
// speedup vs baseline: 3.8153x; 1.1915x over previous
#include <cuda_runtime.h>
#include <cuda_bf16.h>
#include <math_constants.h>
#include <cstdint>

// Problem constants
#define NROWS 8192      // B*H*W = 8*32*32
#define NE    16384
#define KDIM  256
#define NCHUNK 4        // KDIM/64
#define TCM   128       // rows per CTA tile
#define TCN   256       // cols per CTA tile
#define NBLK2 (NE / TCN)    // 64
#define MBLK2 (NROWS / TCM) // 64
#define NZQ   2097152
#define NOUTBLOCKS (NZQ / 256)
// Screening threshold: worst-case deviation of reconstructed-bf16 screening d
// vs exact d: 1.4e-4 (bf16 inputs+TC, Cauchy-Schwarz) + 3.5e-5 (bf16 dot
// store). Capture condition needs THR > delta + 1.4e-4 = 3.2e-4. 6e-4 holds.
#define RESCREEN_THR 6e-4f

#define SWZ(x) ((x) ^ (((x) >> 3) & 0x70))

// GEMM smem: A chunks (128 rows x 128B) x2, B chunks (256 rows x 128B) x2
#define SMA0 0
#define SMA1 16384
#define SMB0 32768
#define SMB1 65536
// Epilogue staging tile (after final sync, aliases mainloop buffers):
// 128 rows x 256 bf16, row stride 544B (16B-aligned, <=2-way bank conflicts)
#define SMEPI 4096
#define LDPB  544
#define SM_TOTAL 98304

// Scratch (device globals; no allocation allowed)
__device__ float  g_t1[NROWS];
__device__ float  g_pd[NROWS * 64];
__device__ float  g_md[NROWS];            // global TC-min per row
__device__ int    g_idx[NROWS];
__device__ double g_lpart[NOUTBLOCKS];
__device__ __align__(16) __nv_bfloat16 g_Aext[(size_t)NROWS * KDIM];   // 4 MB
__device__ __align__(16) __nv_bfloat16 g_Bext[(size_t)NE * KDIM];      // 8 MB
__device__ __align__(16) __nv_bfloat16 g_Db[(size_t)NROWS * NE];       // 256 MB bf16 dots

// ---------------- PTX helpers (all baseline ISA, legal on plain sm_100) ----
__device__ __forceinline__ uint32_t smem_u32(const void* p) {
    uint32_t a;
    asm("{ .reg .u64 t; cvta.to.shared.u64 t, %1; cvt.u32.u64 %0, t; }" : "=r"(a) : "l"(p));
    return a;
}
__device__ __forceinline__ void cp16(uint32_t d, const void* s) {
    asm volatile("cp.async.cg.shared.global [%0], [%1], 16;" :: "r"(d), "l"(s) : "memory");
}
__device__ __forceinline__ void ldm_x4(uint32_t* r, uint32_t a) {
    asm volatile("ldmatrix.sync.aligned.m8n8.x4.shared.b16 {%0,%1,%2,%3}, [%4];"
                 : "=r"(r[0]), "=r"(r[1]), "=r"(r[2]), "=r"(r[3]) : "r"(a));
}
__device__ __forceinline__ void mma16816(float* c, const uint32_t* a,
                                         uint32_t b0, uint32_t b1) {
    asm volatile(
        "mma.sync.aligned.m16n8k16.row.col.f32.bf16.bf16.f32 "
        "{%0,%1,%2,%3}, {%4,%5,%6,%7}, {%8,%9}, {%0,%1,%2,%3};"
        : "+f"(c[0]), "+f"(c[1]), "+f"(c[2]), "+f"(c[3])
        : "r"(a[0]), "r"(a[1]), "r"(a[2]), "r"(a[3]), "r"(b0), "r"(b1));
}

// ---------------------------------------------------------------------------
// K1: per-row ||z||^2.
// ---------------------------------------------------------------------------
__global__ void k_prep(const float* __restrict__ z) {
    int row = blockIdx.x * blockDim.x + threadIdx.x;
    if (row >= NROWS) return;
    int b  = row >> 10;
    int hw = row & 1023;
    const float* p = z + (size_t)b * 262144 + hw;
    float s = 0.0f;
#pragma unroll 8
    for (int c = 0; c < KDIM; c++) {
        float v = p[(size_t)c * 1024];
        s = fmaf(v, v, s);
    }
    g_t1[row] = s;
}

// ---------------------------------------------------------------------------
// K1b: RN-convert emb to bf16 (screening precision only; rescreen repairs).
// ---------------------------------------------------------------------------
__global__ void k_convB(const float* __restrict__ emb) {
    int t = blockIdx.x * 256 + threadIdx.x;
    if (t >= NE * KDIM) return;
    g_Bext[t] = __float2bfloat16(emb[t]);
}

// ---------------------------------------------------------------------------
// K1c: transpose z to row-major [row][k] and RN-convert to bf16.
// ---------------------------------------------------------------------------
__global__ void k_convA(const float* __restrict__ z) {
    __shared__ float s[32][33];
    int tx = threadIdx.x & 31, ty = threadIdx.x >> 5;
    int hw0 = blockIdx.x * 32, c0 = blockIdx.y * 32, b = blockIdx.z;
    s[ty][tx] = z[(size_t)b * 262144 + (size_t)(c0 + ty) * 1024 + hw0 + tx];
    __syncthreads();
    int r = (b << 10) + hw0 + ty;
    int c = c0 + tx;
    g_Aext[(size_t)r * KDIM + c] = __float2bfloat16(s[tx][ty]);
}

// ---------------------------------------------------------------------------
// K2: mma.sync bf16 GEMM (dot over K=256), screening pass.
// CTA 128x256, 512 threads = 16 warps (4m x 4n), warp tile 32x64.
// Epilogue: per-colblock f32 min -> g_pd; bf16 dots staged via smem ->
// fully-coalesced 128B bursts into g_Db.
// ---------------------------------------------------------------------------
__global__ void __launch_bounds__(512, 1) k_gemm_mma() {
    extern __shared__ char smem[];
    const uint32_t sb = smem_u32(smem);
    const int tid  = threadIdx.x;
    const int lane = tid & 31;
    const int warp = tid >> 5;
    const int wm   = warp >> 2;         // 0..3: m block of 32
    const int wn   = warp & 3;          // 0..3: n block of 64
    const int q    = lane >> 2;         // quad id 0..7
    const int qt   = lane & 3;
    const int nb   = blockIdx.x;
    const int mb   = blockIdx.y;
    const int m0   = mb * TCM;
    const int n0   = nb * TCN;

    const char* Ag = (const char*)(g_Aext + (size_t)m0 * KDIM);
    const char* Bg = (const char*)(g_Bext + (size_t)n0 * KDIM);

    // ldmatrix lane address patterns
    const int a_r  = (lane & 7) + ((lane >> 3) & 1) * 8;   // row within m16
    const int a_kh = lane >> 4;                            // k-half
    const int b_r  = (lane & 7) + ((lane >> 4) & 1) * 8;   // row within n16 pair
    const int b_kh = (lane >> 3) & 1;                      // k-half

    float acc[2][8][4];
#pragma unroll
    for (int mt = 0; mt < 2; mt++)
#pragma unroll
        for (int nt = 0; nt < 8; nt++)
#pragma unroll
            for (int r = 0; r < 4; r++) acc[mt][nt][r] = 0.0f;

    // chunk loader: row stride is KDIM*2 = 512 bytes
    auto load_chunk = [&](int ck, int buf) {
        const int koff = ck * 128;
#pragma unroll
        for (int p = 0; p < 2; p++) {
            int idx = tid + p * 512;
            int row = idx >> 3, g = idx & 7;
            cp16(sb + (buf ? SMA1 : SMA0) + (uint32_t)SWZ(row * 128 + g * 16),
                 Ag + (size_t)row * 512 + koff + g * 16);
        }
#pragma unroll
        for (int p = 0; p < 4; p++) {
            int idx = tid + p * 512;
            int row = idx >> 3, g = idx & 7;
            cp16(sb + (buf ? SMB1 : SMB0) + (uint32_t)SWZ(row * 128 + g * 16),
                 Bg + (size_t)row * 512 + koff + g * 16);
        }
    };

    load_chunk(0, 0);
    asm volatile("cp.async.commit_group;" ::: "memory");
    asm volatile("cp.async.wait_group 0;" ::: "memory");
    __syncthreads();

#pragma unroll 1
    for (int ck = 0; ck < NCHUNK; ck++) {
        const int cur = ck & 1;
        if (ck + 1 < NCHUNK) {
            load_chunk(ck + 1, cur ^ 1);
            asm volatile("cp.async.commit_group;" ::: "memory");
        }
        const uint32_t sA = sb + (cur ? SMA1 : SMA0);
        const uint32_t sB = sb + (cur ? SMB1 : SMB0);

#pragma unroll
        for (int kk = 0; kk < 4; kk++) {
            uint32_t a[2][4];
#pragma unroll
            for (int mt = 0; mt < 2; mt++) {
                int row  = wm * 32 + mt * 16 + a_r;
                int byte = row * 128 + (kk * 2 + a_kh) * 16;
                ldm_x4(a[mt], sA + (byte ^ ((byte >> 3) & 0x70)));
            }
#pragma unroll
            for (int ntp = 0; ntp < 4; ntp++) {
                int row  = wn * 64 + ntp * 16 + b_r;
                int byte = row * 128 + (kk * 2 + b_kh) * 16;
                uint32_t bbf[4];
                ldm_x4(bbf, sB + (byte ^ ((byte >> 3) & 0x70)));
#pragma unroll
                for (int mt = 0; mt < 2; mt++) {
                    mma16816(acc[mt][2 * ntp],     a[mt], bbf[0], bbf[1]);
                    mma16816(acc[mt][2 * ntp + 1], a[mt], bbf[2], bbf[3]);
                }
            }
        }
        if (ck + 1 < NCHUNK)
            asm volatile("cp.async.wait_group 0;" ::: "memory");
        __syncthreads();
    }

    // ---- epilogue: f32 colblock min + bf16 dot staging ----
    float* sd = (float*)smem;            // [128][4] floats (2KB, below SMEPI)

#pragma unroll
    for (int s = 0; s < 4; s++) {
        const int mt = s >> 1;
        const int ch = (s & 1) * 2;                 // col pair (c0, c0+1), row rl
        const int rl = wm * 32 + mt * 16 + (s & 1) * 8 + q;
        const float t1 = g_t1[m0 + rl];
        float bd = CUDART_INF_F;
#pragma unroll
        for (int nt = 0; nt < 8; nt++) {
            int c0 = wn * 64 + nt * 8 + qt * 2;
            float d0 = __fsub_rn(t1, __fmul_rn(2.0f, acc[mt][nt][ch]));
            float d1 = __fsub_rn(t1, __fmul_rn(2.0f, acc[mt][nt][ch + 1]));
            bd = fminf(bd, fminf(d0, d1));
            // stage bf16 dot pair (4B store, 4B aligned: c0 even)
            __nv_bfloat162 pr = __floats2bfloat162_rn(acc[mt][nt][ch],
                                                      acc[mt][nt][ch + 1]);
            *(__nv_bfloat162*)(smem + SMEPI + rl * LDPB + c0 * 2) = pr;
        }
#pragma unroll
        for (int o = 1; o <= 2; o <<= 1) {
            float od = __shfl_xor_sync(0xffffffffu, bd, o);
            bd = fminf(bd, od);
        }
        if (qt == 0) sd[rl * 4 + wn] = bd;
    }
    __syncthreads();

    if (tid < 128) {
        float bd = CUDART_INF_F;
#pragma unroll
        for (int w = 0; w < 4; w++) bd = fminf(bd, sd[tid * 4 + w]);
        g_pd[(size_t)(m0 + tid) * NBLK2 + nb] = bd;
    }

    // copy-out: 128 rows x 512B; thread -> 128B contiguous burst
    {
        int rr  = tid >> 2;
        int off = (tid & 3) * 128;      // bytes within the row
        const uint4* src = (const uint4*)(smem + SMEPI + rr * LDPB + off);
        uint4* dst = (uint4*)((char*)(g_Db + (size_t)(m0 + rr) * NE + n0) + off);
#pragma unroll
        for (int i = 0; i < 8; i++) dst[i] = src[i];
    }
}

// ---------------------------------------------------------------------------
// K3: global TC-min per row (screening threshold base).
// ---------------------------------------------------------------------------
__global__ void k_combine() {
    int row  = blockIdx.x * 8 + (threadIdx.x >> 5);
    int lane = threadIdx.x & 31;
    if (row >= NROWS) return;

    float bd = CUDART_INF_F;
    const float* pd = g_pd + (size_t)row * NBLK2;
#pragma unroll
    for (int x = lane; x < NBLK2; x += 32) bd = fminf(bd, pd[x]);
#pragma unroll
    for (int o = 16; o > 0; o >>= 1)
        bd = fminf(bd, __shfl_down_sync(0xffffffffu, bd, o));
    if (lane == 0) g_md[row] = bd;
}

// ---------------------------------------------------------------------------
// K3b: rescreen on bf16 dots. Reconstructed screening d deviates <= 1.75e-4
// from exact; THR covers capture (see header). Exact fp32 recompute +
// lexicographic (d, idx) min = jnp.argmin first-occurrence.
// ---------------------------------------------------------------------------
__global__ void k_rescreen(const float* __restrict__ z,
                           const float* __restrict__ emb,
                           float* __restrict__ out, int out_size) {
    __shared__ float zr[KDIM];
    __shared__ float sbd[256];
    __shared__ int   sbi[256];
    const int row = blockIdx.x;
    const int tid = threadIdx.x;
    const int b = row >> 10, hw = row & 1023;
    zr[tid] = z[(size_t)b * 262144 + (size_t)tid * 1024 + hw];
    __syncthreads();

    const float t1  = g_t1[row];
    const float thr = g_md[row] + RESCREEN_THR;
    const __nv_bfloat16* drow = g_Db + (size_t)row * NE;

    float bd = CUDART_INF_F;
    int   bi = 0x7fffffff;
#pragma unroll 1
    for (int base = tid * 8; base < NE; base += 2048) {
        uint4 v = *(const uint4*)(drow + base);
        const __nv_bfloat162* p2 = (const __nv_bfloat162*)&v;
#pragma unroll
        for (int j = 0; j < 8; j++) {
            float dot = __bfloat162float(((const __nv_bfloat16*)p2)[j]);
            float dv  = __fsub_rn(t1, __fmul_rn(2.0f, dot));
            if (dv <= thr) {
                int col = base + j;
                const float* e = emb + (size_t)col * KDIM;
                float s = 0.0f;
#pragma unroll 8
                for (int k = 0; k < KDIM; k++) s = fmaf(zr[k], e[k], s);
                float dex = __fsub_rn(t1, __fmul_rn(2.0f, s));
                if (dex < bd || (dex == bd && col < bi)) { bd = dex; bi = col; }
            }
        }
    }
    sbd[tid] = bd; sbi[tid] = bi;
    __syncthreads();
#pragma unroll
    for (int o = 128; o > 0; o >>= 1) {
        if (tid < o) {
            float od = sbd[tid + o]; int oi = sbi[tid + o];
            if (od < sbd[tid] || (od == sbd[tid] && oi < sbi[tid])) {
                sbd[tid] = od; sbi[tid] = oi;
            }
        }
        __syncthreads();
    }
    if (tid == 0) {
        g_idx[row] = sbi[0];
        int pos = NZQ + 1 + row;
        if (pos < out_size) out[pos] = (float)sbi[0];
    }
}

// ---------------------------------------------------------------------------
// K4: z_q gather + STE output + per-block loss partials (exact fp32 emulation).
// ---------------------------------------------------------------------------
__global__ void k_out(const float* __restrict__ z, const float* __restrict__ emb,
                      float* __restrict__ out, int out_size) {
    int pos = blockIdx.x * 256 + threadIdx.x;
    double contrib = 0.0;
    if (pos < NZQ) {
        int b   = pos >> 18;
        int r   = pos & 262143;
        int c   = r >> 10;
        int hw  = r & 1023;
        int row = (b << 10) + hw;
        int idx = g_idx[row];
        float ztv   = z[pos];
        float zq    = emb[(size_t)idx * 256 + c];
        float delta = __fsub_rn(zq, ztv);
        if (pos < out_size) out[pos] = __fadd_rn(ztv, delta);
        contrib = (double)__fmul_rn(delta, delta);
    }
    __shared__ double s[256];
    s[threadIdx.x] = contrib;
    __syncthreads();
#pragma unroll
    for (int o = 128; o > 0; o >>= 1) {
        if (threadIdx.x < o) s[threadIdx.x] += s[threadIdx.x + o];
        __syncthreads();
    }
    if (threadIdx.x == 0) g_lpart[blockIdx.x] = s[0];
}

// ---------------------------------------------------------------------------
// K5: deterministic final loss. loss = fl(m + fl(0.25*m)), m = fl32(sum/NZQ).
// ---------------------------------------------------------------------------
__global__ void k_loss(float* __restrict__ out, int out_size) {
    __shared__ double s[256];
    double acc = 0.0;
    for (int x = threadIdx.x; x < NOUTBLOCKS; x += 256) acc += g_lpart[x];
    s[threadIdx.x] = acc;
    __syncthreads();
#pragma unroll
    for (int o = 128; o > 0; o >>= 1) {
        if (threadIdx.x < o) s[threadIdx.x] += s[threadIdx.x + o];
        __syncthreads();
    }
    if (threadIdx.x == 0 && NZQ < out_size) {
        float m = (float)(s[0] / (double)NZQ);
        out[NZQ] = __fadd_rn(m, __fmul_rn(0.25f, m));
    }
}

// ---------------------------------------------------------------------------
extern "C" void kernel_launch(void* const* d_in, const int* in_sizes, int n_in,
                              void* d_out, int out_size) {
    const float* z   = (const float*)d_in[0];   // [8,256,32,32]
    const float* emb = (const float*)d_in[1];   // [16384,256]
    float* out = (float*)d_out;

    cudaFuncSetAttribute(k_gemm_mma, cudaFuncAttributeMaxDynamicSharedMemorySize,
                         SM_TOTAL);

    k_prep<<<NROWS / 256, 256>>>(z);
    k_convB<<<(NE * KDIM) / 256, 256>>>(emb);
    {
        dim3 g(32, 8, 8);   // hw-tiles, c-tiles, b
        k_convA<<<g, dim3(32 * 32)>>>(z);
    }
    {
        dim3 g(NBLK2, MBLK2);   // 64 x 64
        k_gemm_mma<<<g, 512, SM_TOTAL>>>();
    }
    k_combine<<<NROWS / 8, 256>>>();
    k_rescreen<<<NROWS, 256>>>(z, emb, out, out_size);
    k_out<<<NOUTBLOCKS, 256>>>(z, emb, out, out_size);
    k_loss<<<1, 256>>>(out, out_size);
}